// round 5
// baseline (speedup 1.0000x reference)
#include <cuda_runtime.h>
#include <cstdint>

#define NBOX     262144
#define ROWLEN   85
#define NBUCKET  65536             // reversed top-16 mantissa bits
#define NPART    64                // NBUCKET / 1024
#define MAXSEL   300
#define CHUNK    256
#define NWORDS   (CHUNK / 32)
#define LIMIT    6144              // sorted-prefix cutoff (NMS consumes ~310)
#define GRID     148
#define TPB      1024
#define NWARPS_T (GRID * (TPB / 32))   // 4736
#define GSTRIDE  (GRID * TPB)          // 151552

// ---------------- device scratch (zero-initialized at module load; -------
// ---------------- re-zeroed at the end of every run) ----------------------
__device__ uint32_t            g_hist[NBUCKET];
__device__ uint32_t            g_base[NBUCKET];
__device__ uint32_t            g_part[NPART];
__device__ uint32_t            g_count;
__device__ unsigned long long  g_ucand[NBOX];     // dense, 0 = invalid
__device__ unsigned long long  g_sorted[NBOX];
__device__ uint32_t            g_bar_count;
__device__ volatile uint32_t   g_bar_gen;

// key layout: mantissa(23) << 41 | inv_idx(18) << 23 | cls(7) << 16 | rank(16)
// desc key order = desc score, asc index on ties. cls/rank below unique idx bits.
// bucket rb = (NBUCKET-1) - (mantissa >> 7): ascending rb == descending score.

// ---------------- software grid barrier ----------------
__device__ __forceinline__ void grid_sync() {
    __syncthreads();
    if (threadIdx.x == 0) {
        __threadfence();                       // release (CCTL.IVALL on sm_103a)
        uint32_t gen = g_bar_gen;
        if (atomicAdd(&g_bar_count, 1u) == gridDim.x - 1) {
            g_bar_count = 0;
            __threadfence();
            g_bar_gen = gen + 1;
        } else {
            while (g_bar_gen == gen) { __nanosleep(64); }
        }
        __threadfence();                       // acquire + L1 invalidate
    }
    __syncthreads();
}

// ---------------- exact IoU > 0.5 decision (match XLA association) -------
__device__ __forceinline__ bool iou_gt(float4 a, float4 b) {
    float y1 = fmaxf(a.x, b.x);
    float x1 = fmaxf(a.y, b.y);
    float y2 = fminf(a.z, b.z);
    float x2 = fminf(a.w, b.w);
    float ih = fmaxf(__fsub_rn(y2, y1), 0.0f);
    float iw = fmaxf(__fsub_rn(x2, x1), 0.0f);
    float inter = __fmul_rn(ih, iw);
    float aa = __fmul_rn(fmaxf(__fsub_rn(a.z, a.x), 0.0f),
                         fmaxf(__fsub_rn(a.w, a.y), 0.0f));
    float ab = __fmul_rn(fmaxf(__fsub_rn(b.z, b.x), 0.0f),
                         fmaxf(__fsub_rn(b.w, b.y), 0.0f));
    float denom = __fadd_rn(__fsub_rn(__fadd_rn(aa, ab), inter), 1e-9f);
    return __fdiv_rn(inter, denom) > 0.5f;
}

// ---------------- fused persistent kernel ----------------
__global__ __launch_bounds__(TPB, 1)
void fused_kernel(const float* __restrict__ in, float* __restrict__ out,
                  int out_size) {
    __shared__ uint32_t sh_scan[1024];
    __shared__ uint32_t sh_part[NPART];
    // NMS shared (block 0 only)
    __shared__ float4             s_kept[MAXSEL];
    __shared__ float4             s_cbox[CHUNK];
    __shared__ unsigned long long s_ckey[CHUNK];
    __shared__ uint32_t           s_supp[NWORDS];
    __shared__ uint32_t           s_nzw[NWORDS];
    __shared__ uint32_t           s_mask[CHUNK][NWORDS];
    __shared__ float              s_selscore[MAXSEL];
    __shared__ int                s_selcls[MAXSEL];
    __shared__ int                s_nsel, s_total, s_stop;

    const int tid  = threadIdx.x;
    const int gtid = blockIdx.x * TPB + tid;
    const int lane = tid & 31;

    // ---- P0: zero the output (all blocks; ordered before block0's writes
    // by the grid syncs below) ----
    for (int i = gtid; i < out_size; i += GSTRIDE) out[i] = 0.0f;

    // ---- P1: score / class / threshold, dense key write + histograms ----
    {
        int wid_g = blockIdx.x * (TPB / 32) + (tid >> 5);
        #pragma unroll 2
        for (int box = wid_g; box < NBOX; box += NWARPS_T) {
            const float* row = in + (size_t)box * ROWLEN;
            float conf = __ldg(row + 4);

            uint32_t b0 = 0, b1 = 0, b2 = 0;
            if (lane >= 5)  b0 = __float_as_uint(__fmul_rn(conf, __ldg(row + lane)));
            b1 = __float_as_uint(__fmul_rn(conf, __ldg(row + 32 + lane)));
            if (lane < 21)  b2 = __float_as_uint(__fmul_rn(conf, __ldg(row + 64 + lane)));

            uint32_t lmax = max(b0, max(b1, b2));
            uint32_t wmax = __reduce_max_sync(0xFFFFFFFFu, lmax);

            uint32_t lcls = 255u;
            if (b2 == wmax && lane < 21) lcls = (uint32_t)(lane + 59);
            if (b1 == wmax)              lcls = (uint32_t)(lane + 27);
            if (b0 == wmax && lane >= 5) lcls = (uint32_t)(lane - 5);
            uint32_t wcls = __reduce_min_sync(0xFFFFFFFFu, lcls);

            if (lane == 0) {
                unsigned long long key = 0ull;
                if (__uint_as_float(wmax) >= 0.6f) {
                    uint32_t m  = wmax & 0x7FFFFFu;            // exponent fixed (126)
                    uint32_t rb = (NBUCKET - 1u) - (m >> 7);   // reversed bucket
                    uint32_t rank = atomicAdd(&g_hist[rb], 1u);
                    atomicAdd(&g_part[rb >> 10], 1u);          // group partial
                    key = ((unsigned long long)m << 41) |
                          ((unsigned long long)(NBOX - 1 - box) << 23) |
                          ((unsigned long long)wcls << 16) |
                          (unsigned long long)(rank & 0xFFFFu);
                }
                g_ucand[box] = key;
            }
        }
    }
    grid_sync();

    // ---- P2: per-bucket base (blocks 0..63; redundant 64-wide part scan) -
    if (blockIdx.x < NPART) {
        if (tid < NPART) sh_part[tid] = __ldcg(&g_part[tid]);
        __syncthreads();
        if (tid == 0) {
            uint32_t run = 0;
            #pragma unroll
            for (int k = 0; k < NPART; k++) { uint32_t c = sh_part[k]; sh_part[k] = run; run += c; }
            if (blockIdx.x == 0) g_count = run;
        }
        __syncthreads();

        int gid = blockIdx.x * 1024 + tid;
        uint32_t c = __ldcg(&g_hist[gid]);
        sh_scan[tid] = c;
        __syncthreads();
        for (int off = 1; off < 1024; off <<= 1) {
            uint32_t y = 0;
            if (tid >= off) y = sh_scan[tid - off];
            __syncthreads();
            if (tid >= off) sh_scan[tid] += y;
            __syncthreads();
        }
        g_base[gid] = sh_scan[tid] - c + sh_part[blockIdx.x];
    }
    grid_sync();

    // ---- P3: deterministic scatter into sorted-prefix segments ----------
    for (int i = gtid; i < NBOX; i += GSTRIDE) {
        unsigned long long key = __ldcg(&g_ucand[i]);
        if (key == 0ull) continue;
        uint32_t m    = (uint32_t)(key >> 41);
        uint32_t rb   = (NBUCKET - 1u) - (m >> 7);
        uint32_t base = __ldcg(&g_base[rb]);
        if (base >= LIMIT) continue;               // beyond prefix: never consumed
        uint32_t rank = (uint32_t)(key & 0xFFFFu);
        g_sorted[base + rank] = key;
    }
    grid_sync();

    // ---- P4: sort within each participating bucket (thread per bucket) --
    if (gtid < NBUCKET) {
        uint32_t beg = __ldcg(&g_base[gtid]);
        if (beg < LIMIT) {
            uint32_t n = __ldcg(&g_hist[gtid]);
            for (uint32_t i = 1; i < n; i++) {
                unsigned long long k = g_sorted[beg + i];
                uint32_t j = i;
                while (j > 0 && g_sorted[beg + j - 1] < k) {   // descending
                    g_sorted[beg + j] = g_sorted[beg + j - 1];
                    j--;
                }
                g_sorted[beg + j] = k;
            }
        }
    }
    grid_sync();

    // ---- P5: block 0 = chunked greedy NMS + output; others = cleanup ----
    if (blockIdx.x != 0) {
        int zb = (blockIdx.x - 1) * TPB + tid;     // blocks 1..64 cover all buckets
        for (int i = zb; i < NBUCKET; i += (GRID - 1) * TPB) g_hist[i] = 0;
        if (blockIdx.x == 1 && tid < NPART) g_part[tid] = 0;
        return;
    }

    if (tid == 0) {
        s_nsel  = 0;
        s_total = min((int)g_count, LIMIT);
        s_stop  = 0;
    }
    __syncthreads();
    int total = s_total;

    for (int start = 0; start < total; start += CHUNK) {
        if (s_stop) break;
        int m = min(CHUNK, total - start);

        for (int j = tid; j < m; j += TPB) {
            unsigned long long key = __ldcg(&g_sorted[start + j]);
            s_ckey[j] = key;
            int idx = NBOX - 1 - (int)((key >> 23) & 0x3FFFFu);
            const float* r = in + (size_t)idx * ROWLEN;
            s_cbox[j] = make_float4(__ldg(r), __ldg(r + 1), __ldg(r + 2), __ldg(r + 3));
        }
        if (tid < NWORDS) {
            uint32_t w = 0;
            int base = tid * 32;
            #pragma unroll
            for (int b2 = 0; b2 < 32; b2++)
                if (base + b2 >= m) w |= (1u << b2);
            s_supp[tid] = w;
        }
        __syncthreads();

        int nk = s_nsel;
        // (a) suppressed-by-previously-kept, 4 threads per candidate
        {
            int j = tid & (CHUNK - 1);
            int g = tid >> 8;
            bool sup = false;
            if (j < m) {
                float4 bj = s_cbox[j];
                for (int k = g; k < nk; k += 4) {
                    if (iou_gt(s_kept[k], bj)) { sup = true; break; }
                }
            }
            if (sup) atomicOr(&s_supp[j >> 5], 1u << (j & 31));
        }
        // (b) intra-chunk pairwise mask: thread (j, seg) owns 64 k's
        {
            int j   = tid & (CHUNK - 1);
            int seg = tid >> 8;
            uint32_t w0 = 0, w1 = 0;
            if (j < m) {
                float4 bj = s_cbox[j];
                int kb = seg * 64;
                for (int kk = 0; kk < 64; kk++) {
                    int k = kb + kk;
                    if (k < m && k != j && iou_gt(bj, s_cbox[k])) {
                        if (kk < 32) w0 |= (1u << kk);
                        else         w1 |= (1u << (kk - 32));
                    }
                }
            }
            s_mask[j][seg * 2]     = w0;
            s_mask[j][seg * 2 + 1] = w1;
        }
        __syncthreads();

        // (b2) per-candidate "suppresses anything" ballot
        if (tid < CHUNK) {
            uint32_t ored = 0;
            #pragma unroll
            for (int w = 0; w < NWORDS; w++) ored |= s_mask[tid][w];
            uint32_t bal = __ballot_sync(0xFFFFFFFFu, ored != 0u);
            if ((tid & 31) == 0) s_nzw[tid >> 5] = bal;
        }
        __syncthreads();

        // (c) serial bit-scan in registers (thread 0)
        if (tid == 0) {
            uint32_t supp[NWORDS], nzw[NWORDS];
            #pragma unroll
            for (int w = 0; w < NWORDS; w++) { supp[w] = s_supp[w]; nzw[w] = s_nzw[w]; }
            int nsel = s_nsel;
            #pragma unroll
            for (int w = 0; w < NWORDS; w++) {
                uint32_t wv = supp[w];
                while (wv != 0xFFFFFFFFu && nsel < MAXSEL) {
                    int b = __ffs(~wv) - 1;
                    int j = (w << 5) | b;
                    wv |= (1u << b);
                    unsigned long long key = s_ckey[j];
                    s_kept[nsel]     = s_cbox[j];
                    s_selscore[nsel] = __uint_as_float((126u << 23) | (uint32_t)(key >> 41));
                    s_selcls[nsel]   = (int)((key >> 16) & 0x7Fu);
                    nsel++;
                    if (nzw[w] & (1u << b)) {
                        wv |= s_mask[j][w];
                        #pragma unroll
                        for (int w2 = 0; w2 < NWORDS; w2++)
                            if (w2 > w) supp[w2] |= s_mask[j][w2];
                    }
                }
                if (nsel >= MAXSEL) break;
            }
            s_nsel = nsel;
            if (nsel >= MAXSEL) s_stop = 1;
        }
        __syncthreads();
    }

    // output: boxes[300*4] | scores[300] | classes[300] | valid[300]
    int nsel = s_nsel;
    for (int t = tid; t < MAXSEL; t += TPB) {
        float4 bx = make_float4(0.f, 0.f, 0.f, 0.f);
        float sc = 0.f, cl = -1.f, va = 0.f;
        if (t < nsel) {
            bx = s_kept[t];
            sc = s_selscore[t];
            cl = (float)s_selcls[t];
            va = 1.f;
        }
        out[t * 4 + 0] = bx.x;
        out[t * 4 + 1] = bx.y;
        out[t * 4 + 2] = bx.z;
        out[t * 4 + 3] = bx.w;
        out[MAXSEL * 4 + t]              = sc;
        out[MAXSEL * 4 + MAXSEL + t]     = cl;
        out[MAXSEL * 4 + MAXSEL * 2 + t] = va;
    }
}

// ---------------- launch ----------------
extern "C" void kernel_launch(void* const* d_in, const int* in_sizes, int n_in,
                              void* d_out, int out_size) {
    const float* in  = (const float*)d_in[0];
    float*       out = (float*)d_out;
    fused_kernel<<<GRID, TPB>>>(in, out, out_size);
}

// round 6
// speedup vs baseline: 1.6630x; 1.6630x over previous
#include <cuda_runtime.h>
#include <cstdint>

#define NBOX     262144
#define ROWLEN   85
#define NBUCKET  65536             // reversed top-16 mantissa bits
#define NPART    64                // NBUCKET / 1024
#define MAXSEL   300
#define CHUNK    256
#define NWORDS   (CHUNK / 32)
#define LIMIT    6144              // sorted-prefix cutoff (NMS consumes ~310)
#define SB       128               // boxes per score block

// ---------------- device scratch (zeroed at load; re-zeroed each run) ----
__device__ uint32_t            g_hist[NBUCKET];
__device__ uint32_t            g_base[NBUCKET];
__device__ uint32_t            g_part[NPART];
__device__ uint32_t            g_count;
__device__ unsigned long long  g_ucand[NBOX];     // dense, 0 = invalid
__device__ unsigned long long  g_sorted[NBOX];

// key layout: mantissa(23) << 41 | inv_idx(18) << 23 | cls(7) << 16 | rank(16)
// desc key order = desc score, asc index on ties. cls/rank below unique idx bits.
// bucket rb = (NBUCKET-1) - (mantissa >> 7): ascending rb == descending score.

// ---------------- exact IoU > 0.5 (XLA association; areas precomputed) ---
__device__ __forceinline__ bool iou_gt(float4 a, float aa, float4 b, float ab) {
    float y1 = fmaxf(a.x, b.x);
    float x1 = fmaxf(a.y, b.y);
    float y2 = fminf(a.z, b.z);
    float x2 = fminf(a.w, b.w);
    float ih = fmaxf(__fsub_rn(y2, y1), 0.0f);
    float iw = fmaxf(__fsub_rn(x2, x1), 0.0f);
    float inter = __fmul_rn(ih, iw);
    float denom = __fadd_rn(__fsub_rn(__fadd_rn(aa, ab), inter), 1e-9f);
    return __fdiv_rn(inter, denom) > 0.5f;
}
__device__ __forceinline__ float box_area(float4 a) {
    return __fmul_rn(fmaxf(__fsub_rn(a.z, a.x), 0.0f),
                     fmaxf(__fsub_rn(a.w, a.y), 0.0f));
}

// ---------------- P1: smem-staged score / argmax / threshold -------------
__global__ __launch_bounds__(SB) void score_kernel(const float* __restrict__ in) {
    __shared__ float srow[SB * ROWLEN];          // 43520 B
    const int t = threadIdx.x;

    // flat coalesced float4 copy of 128 rows (block base is 16B-aligned:
    // 128*85*4 = 43520 ≡ 0 mod 16)
    const float4* gin = (const float4*)(in + (size_t)blockIdx.x * SB * ROWLEN);
    float4* s4 = (float4*)srow;
    #pragma unroll
    for (int k = t; k < SB * ROWLEN / 4; k += SB) s4[k] = __ldg(&gin[k]);
    __syncthreads();

    // thread t owns row t: exact argmax of conf*prob, first-index tie-break
    const float* r = srow + t * ROWLEN;
    float conf = r[4];
    float s0 = -1.0f, s1 = -1.0f;
    int   c0 = 0,     c1 = 1;
    #pragma unroll 8
    for (int c = 0; c < 80; c += 2) {
        float a = __fmul_rn(conf, r[5 + c]);
        float b = __fmul_rn(conf, r[6 + c]);
        if (a > s0) { s0 = a; c0 = c; }          // strict '>' keeps first index
        if (b > s1) { s1 = b; c1 = c + 1; }
    }
    float best; int bcls;
    if (s1 > s0 || (s1 == s0 && c1 < c0)) { best = s1; bcls = c1; }
    else                                  { best = s0; bcls = c0; }

    int box = blockIdx.x * SB + t;
    unsigned long long key = 0ull;
    if (best >= 0.6f) {
        uint32_t sb   = __float_as_uint(best);
        uint32_t m    = sb & 0x7FFFFFu;              // exponent fixed (126)
        uint32_t rb   = (NBUCKET - 1u) - (m >> 7);   // reversed bucket
        uint32_t rank = atomicAdd(&g_hist[rb], 1u);  // distributed atomic
        atomicAdd(&g_part[rb >> 10], 1u);            // fused group partial
        key = ((unsigned long long)m << 41) |
              ((unsigned long long)(NBOX - 1 - box) << 23) |
              ((unsigned long long)(uint32_t)bcls << 16) |
              (unsigned long long)(rank & 0xFFFFu);
    }
    g_ucand[box] = key;
}

// ---------------- P2: per-bucket base (redundant 64-wide part scan) ------
__global__ void scan_bucket_kernel() {
    __shared__ uint32_t sp[NPART];
    __shared__ uint32_t sh[1024];
    int t = threadIdx.x;

    if (t < NPART) sp[t] = g_part[t];
    __syncthreads();
    if (t == 0) {
        uint32_t run = 0;
        #pragma unroll
        for (int k = 0; k < NPART; k++) { uint32_t c = sp[k]; sp[k] = run; run += c; }
        if (blockIdx.x == 0) g_count = run;
    }
    __syncthreads();

    int gid = blockIdx.x * 1024 + t;
    uint32_t c = g_hist[gid];
    sh[t] = c;
    __syncthreads();
    for (int off = 1; off < 1024; off <<= 1) {
        uint32_t y = 0;
        if (t >= off) y = sh[t - off];
        __syncthreads();
        if (t >= off) sh[t] += y;
        __syncthreads();
    }
    g_base[gid] = sh[t] - c + sp[blockIdx.x];
}

// ---------------- P3: deterministic scatter (prefix only) -----------------
__global__ void scatter_kernel() {
    uint32_t i = blockIdx.x * blockDim.x + threadIdx.x;
    if (i >= NBOX) return;
    unsigned long long key = g_ucand[i];
    if (key == 0ull) return;
    uint32_t m    = (uint32_t)(key >> 41);
    uint32_t rb   = (NBUCKET - 1u) - (m >> 7);
    uint32_t base = g_base[rb];
    if (base >= LIMIT) return;
    uint32_t rank = (uint32_t)(key & 0xFFFFu);
    g_sorted[base + rank] = key;
}

// ---------------- P4: sort within each participating bucket ---------------
__global__ void bucket_sort_kernel() {
    int b = blockIdx.x * blockDim.x + threadIdx.x;
    if (b >= NBUCKET) return;
    uint32_t beg = g_base[b];
    if (beg >= LIMIT) return;
    uint32_t n = g_hist[b];
    for (uint32_t i = 1; i < n; i++) {
        unsigned long long k = g_sorted[beg + i];
        uint32_t j = i;
        while (j > 0 && g_sorted[beg + j - 1] < k) {   // descending
            g_sorted[beg + j] = g_sorted[beg + j - 1];
            j--;
        }
        g_sorted[beg + j] = k;
    }
}

// ---------------- P5: single-block greedy NMS (live-box pruned) -----------
__global__ __launch_bounds__(1024, 1) void nms_kernel(const float* __restrict__ in,
                                                      float* __restrict__ out,
                                                      int out_size) {
    __shared__ float4             s_keptl[MAXSEL];    // live kept only
    __shared__ float              s_karea[MAXSEL];
    __shared__ float4             s_selbox[MAXSEL];   // all selections (output)
    __shared__ float              s_selscore[MAXSEL];
    __shared__ int                s_selcls[MAXSEL];
    __shared__ float4             s_cbox[CHUNK];
    __shared__ float              s_carea[CHUNK];
    __shared__ unsigned long long s_ckey[CHUNK];
    __shared__ uint32_t           s_supp[NWORDS];
    __shared__ uint32_t           s_live[NWORDS];
    __shared__ uint32_t           s_nzw[NWORDS];
    __shared__ uint32_t           s_mask[CHUNK][NWORDS];
    __shared__ int                s_nsel, s_nkl, s_total, s_stop;

    const int tid = threadIdx.x;

    for (int i = tid; i < out_size; i += 1024) out[i] = 0.0f;

    if (tid == 0) {
        s_nsel  = 0;
        s_nkl   = 0;
        s_total = min((int)g_count, LIMIT);
        s_stop  = 0;
    }
    __syncthreads();
    int total = s_total;

    for (int start = 0; start < total; start += CHUNK) {
        if (s_stop) break;
        int m = min(CHUNK, total - start);

        for (int j = tid; j < m; j += 1024) {
            unsigned long long key = __ldcg(&g_sorted[start + j]);
            s_ckey[j] = key;
            int idx = NBOX - 1 - (int)((key >> 23) & 0x3FFFFu);
            const float* r = in + (size_t)idx * ROWLEN;
            float4 b = make_float4(__ldg(r), __ldg(r + 1), __ldg(r + 2), __ldg(r + 3));
            s_cbox[j]  = b;
            s_carea[j] = box_area(b);
        }
        __syncthreads();

        // live bitmap (area > 0) + suppression bitmap init (bits >= m set)
        if (tid < CHUNK) {
            bool alive = (tid < m) && (s_carea[tid] > 0.0f);
            uint32_t bal = __ballot_sync(0xFFFFFFFFu, alive);
            if ((tid & 31) == 0) {
                s_live[tid >> 5] = bal;
                uint32_t w = 0;
                int base = tid;
                #pragma unroll
                for (int b2 = 0; b2 < 32; b2++)
                    if (base + b2 >= m) w |= (1u << b2);
                s_supp[tid >> 5] = w;
            }
        }
        __syncthreads();

        int nkl = s_nkl;
        // (a) suppressed-by-previously-kept (live kept only), 4 thr/candidate
        {
            int j = tid & (CHUNK - 1);
            int g = tid >> 8;
            bool sup = false;
            if (j < m && ((s_live[j >> 5] >> (j & 31)) & 1u)) {
                float4 bj = s_cbox[j];
                float  ab = s_carea[j];
                for (int k = g; k < nkl; k += 4) {
                    if (iou_gt(s_keptl[k], s_karea[k], bj, ab)) { sup = true; break; }
                }
            }
            if (sup) atomicOr(&s_supp[j >> 5], 1u << (j & 31));
        }
        // (b) intra-chunk pairwise mask over live x live only
        {
            int j   = tid & (CHUNK - 1);
            int seg = tid >> 8;
            uint32_t m0 = 0, m1 = 0;
            if (j < m && ((s_live[j >> 5] >> (j & 31)) & 1u)) {
                float4 bj = s_cbox[j];
                float  ab = s_carea[j];
                uint32_t l0 = s_live[seg * 2];
                uint32_t l1 = s_live[seg * 2 + 1];
                if ((j >> 5) == seg * 2)     l0 &= ~(1u << (j & 31));
                if ((j >> 5) == seg * 2 + 1) l1 &= ~(1u << (j & 31));
                while (l0) {
                    int kk = __ffs(l0) - 1; l0 &= l0 - 1;
                    int k = seg * 64 + kk;
                    if (iou_gt(bj, ab, s_cbox[k], s_carea[k])) m0 |= (1u << kk);
                }
                while (l1) {
                    int kk = __ffs(l1) - 1; l1 &= l1 - 1;
                    int k = seg * 64 + 32 + kk;
                    if (iou_gt(bj, ab, s_cbox[k], s_carea[k])) m1 |= (1u << kk);
                }
            }
            s_mask[j][seg * 2]     = m0;
            s_mask[j][seg * 2 + 1] = m1;
        }
        __syncthreads();

        // (b2) per-candidate "suppresses anything" ballot
        if (tid < CHUNK) {
            uint32_t ored = 0;
            #pragma unroll
            for (int w = 0; w < NWORDS; w++) ored |= s_mask[tid][w];
            uint32_t bal = __ballot_sync(0xFFFFFFFFu, ored != 0u);
            if ((tid & 31) == 0) s_nzw[tid >> 5] = bal;
        }
        __syncthreads();

        // (c) serial bit-scan in registers (thread 0)
        if (tid == 0) {
            uint32_t supp[NWORDS], nzw[NWORDS];
            #pragma unroll
            for (int w = 0; w < NWORDS; w++) { supp[w] = s_supp[w]; nzw[w] = s_nzw[w]; }
            int nsel = s_nsel;
            int nk   = s_nkl;
            #pragma unroll
            for (int w = 0; w < NWORDS; w++) {
                uint32_t wv = supp[w];
                while (wv != 0xFFFFFFFFu && nsel < MAXSEL) {
                    int b = __ffs(~wv) - 1;
                    int j = (w << 5) | b;
                    wv |= (1u << b);
                    unsigned long long key = s_ckey[j];
                    float4 bj = s_cbox[j];
                    s_selbox[nsel]   = bj;
                    s_selscore[nsel] = __uint_as_float((126u << 23) | (uint32_t)(key >> 41));
                    s_selcls[nsel]   = (int)((key >> 16) & 0x7Fu);
                    nsel++;
                    float area = s_carea[j];
                    if (area > 0.0f) {
                        s_keptl[nk] = bj;
                        s_karea[nk] = area;
                        nk++;
                    }
                    if (nzw[w] & (1u << b)) {
                        wv |= s_mask[j][w];
                        #pragma unroll
                        for (int w2 = 0; w2 < NWORDS; w2++)
                            if (w2 > w) supp[w2] |= s_mask[j][w2];
                    }
                }
                if (nsel >= MAXSEL) break;
            }
            s_nsel = nsel;
            s_nkl  = nk;
            if (nsel >= MAXSEL) s_stop = 1;
        }
        __syncthreads();
    }

    // output: boxes[300*4] | scores[300] | classes[300] | valid[300]
    int nsel = s_nsel;
    for (int t = tid; t < MAXSEL; t += 1024) {
        float4 bx = make_float4(0.f, 0.f, 0.f, 0.f);
        float sc = 0.f, cl = -1.f, va = 0.f;
        if (t < nsel) {
            bx = s_selbox[t];
            sc = s_selscore[t];
            cl = (float)s_selcls[t];
            va = 1.f;
        }
        out[t * 4 + 0] = bx.x;
        out[t * 4 + 1] = bx.y;
        out[t * 4 + 2] = bx.z;
        out[t * 4 + 3] = bx.w;
        out[MAXSEL * 4 + t]              = sc;
        out[MAXSEL * 4 + MAXSEL + t]     = cl;
        out[MAXSEL * 4 + MAXSEL * 2 + t] = va;
    }

    // re-zero state for the next invocation
    for (int i = tid; i < NBUCKET; i += 1024) g_hist[i] = 0;
    if (tid < NPART) g_part[tid] = 0;
}

// ---------------- launch ----------------
extern "C" void kernel_launch(void* const* d_in, const int* in_sizes, int n_in,
                              void* d_out, int out_size) {
    const float* in  = (const float*)d_in[0];
    float*       out = (float*)d_out;

    score_kernel<<<NBOX / SB, SB>>>(in);
    scan_bucket_kernel<<<NPART, 1024>>>();
    scatter_kernel<<<NBOX / 256, 256>>>();
    bucket_sort_kernel<<<NBUCKET / 256, 256>>>();
    nms_kernel<<<1, 1024>>>(in, out, out_size);
}